// round 4
// baseline (speedup 1.0000x reference)
#include <cuda_runtime.h>
#include <cstdint>

#define N_MAX 100000
#define E_MAX 1600000
#define NUM_GRAPHS 64

// ---------------- scratch (static device globals; no allocation) ----------------
__device__ __align__(16) float d_bufA[N_MAX * 84];   // GEMM output (pre-aggregation)
__device__ __align__(16) float d_bufB[N_MAX * 84];   // aggregation output (next layer input)
__device__ float d_dis[N_MAX];
__device__ int   d_cnt[N_MAX];
__device__ int   d_cursor[N_MAX];
__device__ int   d_rowoff[N_MAX + 1];
__device__ int   d_csr_src[E_MAX];
__device__ float d_csr_w[E_MAX];
__device__ float d_gsum[NUM_GRAPHS * 32];
__device__ float d_gcnt[NUM_GRAPHS];
__device__ int   d_is64_ei;
__device__ int   d_is64_bt;

// ---------------- dtype detection (int32 vs int64 index buffers) ----------------
__global__ void detect_kernel(const unsigned* __restrict__ ei, int ei_words,
                              const unsigned* __restrict__ bt, int bt_words) {
    __shared__ int nz_ei, nz_bt;
    if (threadIdx.x == 0) { nz_ei = 0; nz_bt = 0; }
    __syncthreads();
    int t = threadIdx.x;
    int step_e = max(1, ei_words / 2 / 4096);
    int step_b = max(1, bt_words / 2 / 4096);
    int le = 0, lb = 0;
    for (int k = t; k < 4096; k += 256) {
        long long ie = 2LL * (long long)k * step_e + 1;
        if (ie < ei_words && ei[ie] != 0u) le = 1;
        long long ib = 2LL * (long long)k * step_b + 1;
        if (ib < bt_words && bt[ib] != 0u) lb = 1;
    }
    if (le) atomicOr(&nz_ei, 1);
    if (lb) atomicOr(&nz_bt, 1);
    __syncthreads();
    if (threadIdx.x == 0) {
        d_is64_ei = nz_ei ? 0 : 1;
        d_is64_bt = nz_bt ? 0 : 1;
    }
}

__device__ __forceinline__ int load_idx(const void* p, int is64, long long i, int n) {
    int v = is64 ? (int)((const long long*)p)[i] : ((const int*)p)[i];
    return min(max(v, 0), n - 1);
}

// ---------------- build kernels ----------------
__global__ void zero_kernel(int n) {
    int i = blockIdx.x * blockDim.x + threadIdx.x;
    if (i < n) d_cnt[i] = 0;
    if (i < NUM_GRAPHS * 32) d_gsum[i] = 0.f;
    if (i < NUM_GRAPHS) d_gcnt[i] = 0.f;
}

__global__ void count_kernel(const void* __restrict__ ei, int e, int n) {
    int i = blockIdx.x * blockDim.x + threadIdx.x;
    if (i < e) {
        int d = load_idx(ei, d_is64_ei, (long long)e + i, n);   // dst row
        atomicAdd(&d_cnt[d], 1);
    }
}

// scan + dis fused: dis[i] = rsqrt(cnt[i]+1) computed during the count sweep
__global__ void scan_kernel(int n) {
    __shared__ int sums[1024];
    int t = threadIdx.x;
    int per = (n + 1023) / 1024;
    int start = t * per;
    int end = min(start + per, n);
    int s = 0;
    for (int i = start; i < end; i++) {
        int c = d_cnt[i];
        d_dis[i] = rsqrtf((float)(c + 1));   // +1 self loop; deg >= 1 always
        s += c;
    }
    sums[t] = s;
    __syncthreads();
    for (int off = 1; off < 1024; off <<= 1) {
        int v = (t >= off) ? sums[t - off] : 0;
        __syncthreads();
        sums[t] += v;
        __syncthreads();
    }
    int run = (t == 0) ? 0 : sums[t - 1];
    for (int i = start; i < end; i++) {
        d_rowoff[i] = run;
        d_cursor[i] = run;
        run += d_cnt[i];
    }
    if (t == 1023) d_rowoff[n] = sums[1023];
}

__global__ void fill_kernel(const void* __restrict__ ei, int e, int n) {
    int i = blockIdx.x * blockDim.x + threadIdx.x;
    if (i < e) {
        int is64 = d_is64_ei;
        int s = load_idx(ei, is64, i, n);
        int d = load_idx(ei, is64, (long long)e + i, n);
        int p = atomicAdd(&d_cursor[d], 1);
        p = min(max(p, 0), E_MAX - 1);
        d_csr_src[p] = s;
        d_csr_w[p] = d_dis[s];
    }
}

// ---------------- GEMM: T(=d_bufA) = X @ W, X is [n,K] row-major, W [K,F] row-major ----------------
template <int K, int F>
__global__ void gemm_kernel(const float* __restrict__ Xext, int useB,
                            const float* __restrict__ W, int n) {
    constexpr int TN = (F + 15) / 16;     // cols per thread (strided by 16)
    constexpr int KC = 32;
    __shared__ float xs[KC][129];         // [k][node], pad 129 -> conflict-free
    __shared__ float ws[KC][TN * 16];

    const float* __restrict__ X = useB ? d_bufB : Xext;

    const int tx = threadIdx.x;   // 0..15 (cols)
    const int ty = threadIdx.y;   // 0..15 (rows)
    const int tid = ty * 16 + tx;
    const int nodeBase = blockIdx.x * 128;

    float acc[8][TN];
#pragma unroll
    for (int r = 0; r < 8; r++)
#pragma unroll
        for (int c = 0; c < TN; c++) acc[r][c] = 0.f;

    for (int k0 = 0; k0 < K; k0 += KC) {
        // load X tile (128 nodes x KC), transposed into xs[k][node]
#pragma unroll
        for (int i = 0; i < 4; i++) {
            int node = (tid >> 3) + 32 * i;
            int kq = (tid & 7) * 4;
            int gn = nodeBase + node;
            float v0 = 0.f, v1 = 0.f, v2 = 0.f, v3 = 0.f;
            if (gn < n) {
                int kk = k0 + kq;
                if (kk + 3 < K) {
                    float4 v = *reinterpret_cast<const float4*>(X + (size_t)gn * K + kk);
                    v0 = v.x; v1 = v.y; v2 = v.z; v3 = v.w;
                } else {
                    if (kk + 0 < K) v0 = X[(size_t)gn * K + kk + 0];
                    if (kk + 1 < K) v1 = X[(size_t)gn * K + kk + 1];
                    if (kk + 2 < K) v2 = X[(size_t)gn * K + kk + 2];
                    if (kk + 3 < K) v3 = X[(size_t)gn * K + kk + 3];
                }
            }
            xs[kq + 0][node] = v0;
            xs[kq + 1][node] = v1;
            xs[kq + 2][node] = v2;
            xs[kq + 3][node] = v3;
        }
        // load W tile (KC x TN*16, zero padded)
        for (int i = tid; i < KC * TN * 16; i += 256) {
            int kk = i / (TN * 16), c = i % (TN * 16);
            float wv = 0.f;
            if (k0 + kk < K && c < F) wv = W[(size_t)(k0 + kk) * F + c];
            ws[kk][c] = wv;
        }
        __syncthreads();
#pragma unroll 4
        for (int k = 0; k < KC; k++) {
            float xv[8], wv[TN];
#pragma unroll
            for (int r = 0; r < 8; r++) xv[r] = xs[k][ty + 16 * r];
#pragma unroll
            for (int c = 0; c < TN; c++) wv[c] = ws[k][tx + 16 * c];
#pragma unroll
            for (int r = 0; r < 8; r++)
#pragma unroll
                for (int c = 0; c < TN; c++) acc[r][c] = fmaf(xv[r], wv[c], acc[r][c]);
        }
        __syncthreads();
    }
#pragma unroll
    for (int r = 0; r < 8; r++) {
        int gn = nodeBase + ty + 16 * r;
        if (gn < n) {
#pragma unroll
            for (int c = 0; c < TN; c++) {
                int col = tx + 16 * c;
                if (col < F) d_bufA[(size_t)gn * F + col] = acc[r][c];
            }
        }
    }
}

// ---------------- aggregation: d_bufB = relu(bias + dis_i*(sum_e w_e*T[src] + dis_i*T[i])) ----
// G lane-groups of L=F/4 lanes each process G edges concurrently, cross-group
// reduced at the end via shfl_down. Full-warp shfl stays convergent.
template <int F, int G>
__global__ void agg_kernel(const float* __restrict__ bias, int n) {
    constexpr int L = F / 4;   // float4 lanes per group: 21 / 16 / 8
    int w = (blockIdx.x * blockDim.x + threadIdx.x) >> 5;
    int lane = threadIdx.x & 31;
    if (w >= n) return;

    int grp = lane / L;
    int col = lane - grp * L;
    bool act = grp < G;

    int r0 = d_rowoff[w];
    int r1 = d_rowoff[w + 1];
    float dii = d_dis[w];

    const float4* __restrict__ Tf4 = reinterpret_cast<const float4*>(d_bufA);
    float4 acc = make_float4(0.f, 0.f, 0.f, 0.f);

    for (int e0 = r0; e0 < r1; e0 += 32) {
        int e = e0 + lane;
        int s = 0; float wt = 0.f;
        if (e < r1) { s = d_csr_src[e]; wt = d_csr_w[e]; }
        int cnt = min(32, r1 - e0);
        int iters = (cnt + G - 1) / G;
        for (int jj = 0; jj < iters; jj++) {
            int j = jj * G + grp;
            int ss = __shfl_sync(0xffffffffu, s, j & 31);
            float ww = __shfl_sync(0xffffffffu, wt, j & 31);
            if (act && j < cnt) {
                float4 v = Tf4[(size_t)ss * L + col];
                acc.x = fmaf(ww, v.x, acc.x);
                acc.y = fmaf(ww, v.y, acc.y);
                acc.z = fmaf(ww, v.z, acc.z);
                acc.w = fmaf(ww, v.w, acc.w);
            }
        }
    }
    // cross-group reduction (no-op for G==1)
#pragma unroll
    for (int h = G / 2; h >= 1; h >>= 1) {
        acc.x += __shfl_down_sync(0xffffffffu, acc.x, h * L);
        acc.y += __shfl_down_sync(0xffffffffu, acc.y, h * L);
        acc.z += __shfl_down_sync(0xffffffffu, acc.z, h * L);
        acc.w += __shfl_down_sync(0xffffffffu, acc.w, h * L);
    }
    if (lane < L) {
        float4 t0 = Tf4[(size_t)w * L + lane];
        float4 b = reinterpret_cast<const float4*>(bias)[lane];
        float4 o;
        o.x = fmaxf(b.x + dii * (acc.x + dii * t0.x), 0.f);
        o.y = fmaxf(b.y + dii * (acc.y + dii * t0.y), 0.f);
        o.z = fmaxf(b.z + dii * (acc.z + dii * t0.z), 0.f);
        o.w = fmaxf(b.w + dii * (acc.w + dii * t0.w), 0.f);
        reinterpret_cast<float4*>(d_bufB)[(size_t)w * L + lane] = o;
    }
}

// ---------------- pooling: run-length segmented sum over sorted batch ----------------
__global__ void pool_kernel(const void* __restrict__ batch, int n) {
    int w = (blockIdx.x * blockDim.x + threadIdx.x) >> 5;
    int lane = threadIdx.x & 31;
    int start = w * 128;
    if (start >= n) return;
    int end = min(start + 128, n);
    int is64 = d_is64_bt;

    float acc = 0.f;
    int cur = load_idx(batch, is64, start, NUM_GRAPHS);
    int cnt = 0;
    for (int i = start; i < end; i++) {
        int g = load_idx(batch, is64, i, NUM_GRAPHS);
        if (g != cur) {
            atomicAdd(&d_gsum[cur * 32 + lane], acc);
            if (lane == 0) atomicAdd(&d_gcnt[cur], (float)cnt);
            acc = 0.f; cnt = 0; cur = g;
        }
        acc += d_bufB[(size_t)i * 32 + lane];
        cnt++;
    }
    atomicAdd(&d_gsum[cur * 32 + lane], acc);
    if (lane == 0) atomicAdd(&d_gcnt[cur], (float)cnt);
}

__global__ void final_kernel(const float* __restrict__ Wl, const float* __restrict__ bl,
                             float* __restrict__ out) {
    int t = threadIdx.x;
    int g = t >> 1, o = t & 1;
    if (g < NUM_GRAPHS) {
        float inv = 1.f / fmaxf(d_gcnt[g], 1.f);
        float s = 0.f;
        for (int f = 0; f < 32; f++) s += d_gsum[g * 32 + f] * inv * Wl[f * 2 + o];
        out[g * 2 + o] = s + bl[o];
    }
}

// ---------------- launch ----------------
extern "C" void kernel_launch(void* const* d_in, const int* in_sizes, int n_in,
                              void* d_out, int out_size) {
    const float* x     = (const float*)d_in[0];
    const void*  ei    = d_in[1];
    const void*  batch = d_in[2];
    const float* W1 = (const float*)d_in[3];
    const float* b1 = (const float*)d_in[4];
    const float* W2 = (const float*)d_in[5];
    const float* b2 = (const float*)d_in[6];
    const float* W3 = (const float*)d_in[7];
    const float* b3 = (const float*)d_in[8];
    const float* Wl = (const float*)d_in[9];
    const float* bl = (const float*)d_in[10];
    float* out = (float*)d_out;

    int N = in_sizes[0] / 128;
    int E = in_sizes[1] / 2;

    // dtype probe + graph structure (rebuilt every replay; deterministic work)
    detect_kernel<<<1, 256>>>((const unsigned*)ei, in_sizes[1],
                              (const unsigned*)batch, in_sizes[2]);
    zero_kernel<<<(N + 255) / 256, 256>>>(N);
    count_kernel<<<(E + 255) / 256, 256>>>(ei, E, N);
    scan_kernel<<<1, 1024>>>(N);
    fill_kernel<<<(E + 255) / 256, 256>>>(ei, E, N);

    dim3 gthr(16, 16);
    int gblk = (N + 127) / 128;
    int ablk = (N + 7) / 8;   // 8 warps/block, warp per node

    // layer 1: 128 -> 84
    gemm_kernel<128, 84><<<gblk, gthr>>>(x, 0, W1, N);
    agg_kernel<84, 1><<<ablk, 256>>>(b1, N);
    // layer 2: 84 -> 64
    gemm_kernel<84, 64><<<gblk, gthr>>>(nullptr, 1, W2, N);
    agg_kernel<64, 2><<<ablk, 256>>>(b2, N);
    // layer 3: 64 -> 32
    gemm_kernel<64, 32><<<gblk, gthr>>>(nullptr, 1, W3, N);
    agg_kernel<32, 4><<<ablk, 256>>>(b3, N);

    // mean pool + linear head
    int pwarps = (N + 127) / 128;
    pool_kernel<<<(pwarps + 7) / 8, 256>>>(batch, N);
    final_kernel<<<1, 128>>>(Wl, bl, out);
}

// round 5
// speedup vs baseline: 1.4059x; 1.4059x over previous
#include <cuda_runtime.h>
#include <cstdint>

#define N_MAX 100000
#define E_MAX 1600000
#define NUM_GRAPHS 64
#define SCAN_BLK 512
#define MAX_BLOCKS 1024   // ceil(N_MAX/SCAN_BLK) = 196 << 1024

// ---------------- scratch (static device globals; no allocation) ----------------
__device__ __align__(16) float d_bufA[N_MAX * 84];   // GEMM output (pre-aggregation)
__device__ __align__(16) float d_bufB[N_MAX * 84];   // aggregation output (next layer input)
__device__ float d_dis[N_MAX];
__device__ int   d_cnt[N_MAX];
__device__ int   d_cursor[N_MAX];
__device__ int   d_rowoff[N_MAX + 1];
__device__ int   d_blocksum[MAX_BLOCKS];
__device__ int   d_blockoff[MAX_BLOCKS];
__device__ int   d_csr_src[E_MAX];
__device__ float d_csr_w[E_MAX];
__device__ float d_gsum[NUM_GRAPHS * 32];
__device__ float d_gcnt[NUM_GRAPHS];
__device__ int   d_is64_ei;
__device__ int   d_is64_bt;

// ---------------- dtype detection (int32 vs int64 index buffers) ----------------
__global__ void detect_kernel(const unsigned* __restrict__ ei, int ei_words,
                              const unsigned* __restrict__ bt, int bt_words) {
    __shared__ int nz_ei, nz_bt;
    if (threadIdx.x == 0) { nz_ei = 0; nz_bt = 0; }
    __syncthreads();
    int t = threadIdx.x;
    int step_e = max(1, ei_words / 2 / 4096);
    int step_b = max(1, bt_words / 2 / 4096);
    int le = 0, lb = 0;
    for (int k = t; k < 4096; k += 256) {
        long long ie = 2LL * (long long)k * step_e + 1;
        if (ie < ei_words && ei[ie] != 0u) le = 1;
        long long ib = 2LL * (long long)k * step_b + 1;
        if (ib < bt_words && bt[ib] != 0u) lb = 1;
    }
    if (le) atomicOr(&nz_ei, 1);
    if (lb) atomicOr(&nz_bt, 1);
    __syncthreads();
    if (threadIdx.x == 0) {
        d_is64_ei = nz_ei ? 0 : 1;
        d_is64_bt = nz_bt ? 0 : 1;
    }
}

__device__ __forceinline__ int load_idx(const void* p, int is64, long long i, int n) {
    int v = is64 ? (int)((const long long*)p)[i] : ((const int*)p)[i];
    return min(max(v, 0), n - 1);
}

// ---------------- build kernels ----------------
__global__ void zero_kernel(int n) {
    int i = blockIdx.x * blockDim.x + threadIdx.x;
    if (i < n) d_cnt[i] = 0;
    if (i < NUM_GRAPHS * 32) d_gsum[i] = 0.f;
    if (i < NUM_GRAPHS) d_gcnt[i] = 0.f;
}

__global__ void count_kernel(const void* __restrict__ ei, int e, int n) {
    int i = blockIdx.x * blockDim.x + threadIdx.x;
    if (i < e) {
        int d = load_idx(ei, d_is64_ei, (long long)e + i, n);   // dst row
        atomicAdd(&d_cnt[d], 1);
    }
}

// -------- device-wide scan, 3 kernels --------
// 1) per-block sums (+ fused dis computation)
__global__ void block_sum_kernel(int n) {
    __shared__ int red[SCAN_BLK / 32];
    int i = blockIdx.x * SCAN_BLK + threadIdx.x;
    int v = 0;
    if (i < n) {
        v = d_cnt[i];
        d_dis[i] = rsqrtf((float)(v + 1));   // +1 self loop; deg >= 1 always
    }
    int s = v;
#pragma unroll
    for (int h = 16; h >= 1; h >>= 1) s += __shfl_down_sync(0xffffffffu, s, h);
    if ((threadIdx.x & 31) == 0) red[threadIdx.x >> 5] = s;
    __syncthreads();
    if (threadIdx.x < SCAN_BLK / 32) {
        int t = red[threadIdx.x];
#pragma unroll
        for (int h = SCAN_BLK / 64; h >= 1; h >>= 1)
            t += __shfl_down_sync(0xffffffffu, t, h);
        if (threadIdx.x == 0) d_blocksum[blockIdx.x] = t;
    }
}

// 2) single block scans the (few hundred) partials
__global__ void scan_partials_kernel(int nb, int e) {
    __shared__ int s[MAX_BLOCKS];
    int t = threadIdx.x;
    int v = (t < nb) ? d_blocksum[t] : 0;
    s[t] = v;
    __syncthreads();
    for (int off = 1; off < MAX_BLOCKS; off <<= 1) {
        int u = (t >= off) ? s[t - off] : 0;
        __syncthreads();
        s[t] += u;
        __syncthreads();
    }
    if (t < nb) d_blockoff[t] = s[t] - v;   // exclusive
}

// 3) per-block exclusive scan + base offset
__global__ void fill_offsets_kernel(int n) {
    __shared__ int s[SCAN_BLK];
    int i = blockIdx.x * SCAN_BLK + threadIdx.x;
    int v = (i < n) ? d_cnt[i] : 0;
    s[threadIdx.x] = v;
    __syncthreads();
    for (int off = 1; off < SCAN_BLK; off <<= 1) {
        int u = (threadIdx.x >= off) ? s[threadIdx.x - off] : 0;
        __syncthreads();
        s[threadIdx.x] += u;
        __syncthreads();
    }
    int excl = s[threadIdx.x] - v + d_blockoff[blockIdx.x];
    if (i < n) {
        d_rowoff[i] = excl;
        d_cursor[i] = excl;
        if (i == n - 1) d_rowoff[n] = excl + v;
    }
}

__global__ void fill_kernel(const void* __restrict__ ei, int e, int n) {
    int i = blockIdx.x * blockDim.x + threadIdx.x;
    if (i < e) {
        int is64 = d_is64_ei;
        int s = load_idx(ei, is64, i, n);
        int d = load_idx(ei, is64, (long long)e + i, n);
        int p = atomicAdd(&d_cursor[d], 1);
        p = min(max(p, 0), E_MAX - 1);
        d_csr_src[p] = s;
        d_csr_w[p] = d_dis[s];
    }
}

// ---------------- GEMM: T(=d_bufA) = X @ W, X is [n,K] row-major, W [K,F] row-major ----------------
template <int K, int F>
__global__ void gemm_kernel(const float* __restrict__ Xext, int useB,
                            const float* __restrict__ W, int n) {
    constexpr int TN = (F + 15) / 16;     // cols per thread (strided by 16)
    constexpr int KC = 32;
    __shared__ float xs[KC][129];         // [k][node], pad 129 -> conflict-free
    __shared__ float ws[KC][TN * 16];

    const float* __restrict__ X = useB ? d_bufB : Xext;

    const int tx = threadIdx.x;   // 0..15 (cols)
    const int ty = threadIdx.y;   // 0..15 (rows)
    const int tid = ty * 16 + tx;
    const int nodeBase = blockIdx.x * 128;

    float acc[8][TN];
#pragma unroll
    for (int r = 0; r < 8; r++)
#pragma unroll
        for (int c = 0; c < TN; c++) acc[r][c] = 0.f;

    for (int k0 = 0; k0 < K; k0 += KC) {
        // load X tile (128 nodes x KC), transposed into xs[k][node]
#pragma unroll
        for (int i = 0; i < 4; i++) {
            int node = (tid >> 3) + 32 * i;
            int kq = (tid & 7) * 4;
            int gn = nodeBase + node;
            float v0 = 0.f, v1 = 0.f, v2 = 0.f, v3 = 0.f;
            if (gn < n) {
                int kk = k0 + kq;
                if (kk + 3 < K) {
                    float4 v = *reinterpret_cast<const float4*>(X + (size_t)gn * K + kk);
                    v0 = v.x; v1 = v.y; v2 = v.z; v3 = v.w;
                } else {
                    if (kk + 0 < K) v0 = X[(size_t)gn * K + kk + 0];
                    if (kk + 1 < K) v1 = X[(size_t)gn * K + kk + 1];
                    if (kk + 2 < K) v2 = X[(size_t)gn * K + kk + 2];
                    if (kk + 3 < K) v3 = X[(size_t)gn * K + kk + 3];
                }
            }
            xs[kq + 0][node] = v0;
            xs[kq + 1][node] = v1;
            xs[kq + 2][node] = v2;
            xs[kq + 3][node] = v3;
        }
        // load W tile (KC x TN*16, zero padded)
        for (int i = tid; i < KC * TN * 16; i += 256) {
            int kk = i / (TN * 16), c = i % (TN * 16);
            float wv = 0.f;
            if (k0 + kk < K && c < F) wv = W[(size_t)(k0 + kk) * F + c];
            ws[kk][c] = wv;
        }
        __syncthreads();
#pragma unroll 4
        for (int k = 0; k < KC; k++) {
            float xv[8], wv[TN];
#pragma unroll
            for (int r = 0; r < 8; r++) xv[r] = xs[k][ty + 16 * r];
#pragma unroll
            for (int c = 0; c < TN; c++) wv[c] = ws[k][tx + 16 * c];
#pragma unroll
            for (int r = 0; r < 8; r++)
#pragma unroll
                for (int c = 0; c < TN; c++) acc[r][c] = fmaf(xv[r], wv[c], acc[r][c]);
        }
        __syncthreads();
    }
#pragma unroll
    for (int r = 0; r < 8; r++) {
        int gn = nodeBase + ty + 16 * r;
        if (gn < n) {
#pragma unroll
            for (int c = 0; c < TN; c++) {
                int col = tx + 16 * c;
                if (col < F) d_bufA[(size_t)gn * F + col] = acc[r][c];
            }
        }
    }
}

// ---------------- aggregation: d_bufB = relu(bias + dis_i*(sum_e w_e*T[src] + dis_i*T[i])) ----------------
template <int F>
__global__ void agg_kernel(const float* __restrict__ bias, int n) {
    constexpr int L = F / 4;   // active float4 lanes: 21 / 16 / 8
    int w = (blockIdx.x * blockDim.x + threadIdx.x) >> 5;
    int lane = threadIdx.x & 31;
    if (w >= n) return;

    int r0 = d_rowoff[w];
    int r1 = d_rowoff[w + 1];
    float dii = d_dis[w];

    const float4* __restrict__ Tf4 = reinterpret_cast<const float4*>(d_bufA);
    float4 acc = make_float4(0.f, 0.f, 0.f, 0.f);
    if (lane < L) {
        float4 t0 = Tf4[(size_t)w * L + lane];
        acc.x = dii * t0.x; acc.y = dii * t0.y; acc.z = dii * t0.z; acc.w = dii * t0.w;
    }
    for (int e0 = r0; e0 < r1; e0 += 32) {
        int e = e0 + lane;
        int s = 0; float wt = 0.f;
        if (e < r1) { s = d_csr_src[e]; wt = d_csr_w[e]; }
        int cnt = min(32, r1 - e0);
        for (int j = 0; j < cnt; j++) {
            int ss = __shfl_sync(0xffffffffu, s, j);
            float ww = __shfl_sync(0xffffffffu, wt, j);
            if (lane < L) {
                float4 v = Tf4[(size_t)ss * L + lane];
                acc.x = fmaf(ww, v.x, acc.x);
                acc.y = fmaf(ww, v.y, acc.y);
                acc.z = fmaf(ww, v.z, acc.z);
                acc.w = fmaf(ww, v.w, acc.w);
            }
        }
    }
    if (lane < L) {
        float4 b = reinterpret_cast<const float4*>(bias)[lane];
        float4 o;
        o.x = fmaxf(b.x + dii * acc.x, 0.f);
        o.y = fmaxf(b.y + dii * acc.y, 0.f);
        o.z = fmaxf(b.z + dii * acc.z, 0.f);
        o.w = fmaxf(b.w + dii * acc.w, 0.f);
        reinterpret_cast<float4*>(d_bufB)[(size_t)w * L + lane] = o;
    }
}

// ---------------- pooling: run-length segmented sum over sorted batch ----------------
__global__ void pool_kernel(const void* __restrict__ batch, int n) {
    int w = (blockIdx.x * blockDim.x + threadIdx.x) >> 5;
    int lane = threadIdx.x & 31;
    int start = w * 128;
    if (start >= n) return;
    int end = min(start + 128, n);
    int is64 = d_is64_bt;

    float acc = 0.f;
    int cur = load_idx(batch, is64, start, NUM_GRAPHS);
    int cnt = 0;
    for (int i = start; i < end; i++) {
        int g = load_idx(batch, is64, i, NUM_GRAPHS);
        if (g != cur) {
            atomicAdd(&d_gsum[cur * 32 + lane], acc);
            if (lane == 0) atomicAdd(&d_gcnt[cur], (float)cnt);
            acc = 0.f; cnt = 0; cur = g;
        }
        acc += d_bufB[(size_t)i * 32 + lane];
        cnt++;
    }
    atomicAdd(&d_gsum[cur * 32 + lane], acc);
    if (lane == 0) atomicAdd(&d_gcnt[cur], (float)cnt);
}

__global__ void final_kernel(const float* __restrict__ Wl, const float* __restrict__ bl,
                             float* __restrict__ out) {
    int t = threadIdx.x;
    int g = t >> 1, o = t & 1;
    if (g < NUM_GRAPHS) {
        float inv = 1.f / fmaxf(d_gcnt[g], 1.f);
        float s = 0.f;
        for (int f = 0; f < 32; f++) s += d_gsum[g * 32 + f] * inv * Wl[f * 2 + o];
        out[g * 2 + o] = s + bl[o];
    }
}

// ---------------- launch ----------------
extern "C" void kernel_launch(void* const* d_in, const int* in_sizes, int n_in,
                              void* d_out, int out_size) {
    const float* x     = (const float*)d_in[0];
    const void*  ei    = d_in[1];
    const void*  batch = d_in[2];
    const float* W1 = (const float*)d_in[3];
    const float* b1 = (const float*)d_in[4];
    const float* W2 = (const float*)d_in[5];
    const float* b2 = (const float*)d_in[6];
    const float* W3 = (const float*)d_in[7];
    const float* b3 = (const float*)d_in[8];
    const float* Wl = (const float*)d_in[9];
    const float* bl = (const float*)d_in[10];
    float* out = (float*)d_out;

    int N = in_sizes[0] / 128;
    int E = in_sizes[1] / 2;
    int nScanBlk = (N + SCAN_BLK - 1) / SCAN_BLK;

    // dtype probe + graph structure (rebuilt every replay; deterministic work)
    detect_kernel<<<1, 256>>>((const unsigned*)ei, in_sizes[1],
                              (const unsigned*)batch, in_sizes[2]);
    zero_kernel<<<(N + 255) / 256, 256>>>(N);
    count_kernel<<<(E + 255) / 256, 256>>>(ei, E, N);
    block_sum_kernel<<<nScanBlk, SCAN_BLK>>>(N);
    scan_partials_kernel<<<1, MAX_BLOCKS>>>(nScanBlk, E);
    fill_offsets_kernel<<<nScanBlk, SCAN_BLK>>>(N);
    fill_kernel<<<(E + 255) / 256, 256>>>(ei, E, N);

    dim3 gthr(16, 16);
    int gblk = (N + 127) / 128;
    int ablk = (N + 7) / 8;   // 8 warps/block, warp per node

    // layer 1: 128 -> 84
    gemm_kernel<128, 84><<<gblk, gthr>>>(x, 0, W1, N);
    agg_kernel<84><<<ablk, 256>>>(b1, N);
    // layer 2: 84 -> 64
    gemm_kernel<84, 64><<<gblk, gthr>>>(nullptr, 1, W2, N);
    agg_kernel<64><<<ablk, 256>>>(b2, N);
    // layer 3: 64 -> 32
    gemm_kernel<64, 32><<<gblk, gthr>>>(nullptr, 1, W3, N);
    agg_kernel<32><<<ablk, 256>>>(b3, N);

    // mean pool + linear head
    int pwarps = (N + 127) / 128;
    pool_kernel<<<(pwarps + 7) / 8, 256>>>(batch, N);
    final_kernel<<<1, 128>>>(Wl, bl, out);
}